// round 1
// baseline (speedup 1.0000x reference)
#include <cuda_runtime.h>
#include <cuda_bf16.h>

#define IMG_H 512
#define IMG_W 512
#define FXc 500.0f
#define FYc 500.0f
#define CXc 256.0f
#define CYc 256.0f
#define NG  256

// Sorted, precomputed per-gaussian parameters.
// Layout per gaussian (3 x float4):
//   [0] = { mu0*s0, mu1*s1, mu2*s2, s0 }
//   [1] = { s1, s2, m2, a0 }          with m2 = sum(mu_k^2 * s_k)
//   [2] = { c0, c1, c2, 0 }
__device__ float4 g_sorted[NG * 3];

__global__ void prep_kernel(const float* __restrict__ pos,
                            const float* __restrict__ ls,
                            const float* __restrict__ rop,
                            const float* __restrict__ col) {
    const int i = threadIdx.x;
    __shared__ float zs[NG];
    const float z = pos[i * 3 + 2];
    zs[i] = z;
    __syncthreads();

    // Stable rank (matches jnp.argsort ascending, stable on ties).
    int rank = 0;
#pragma unroll 16
    for (int j = 0; j < NG; j++) {
        const float zj = zs[j];
        rank += (zj < z) || (zj == z && j < i);
    }

    const float mu0 = pos[i * 3 + 0];
    const float mu1 = pos[i * 3 + 1];
    const float mu2 = z;

    float e0 = expf(ls[i * 3 + 0]);
    float e1 = expf(ls[i * 3 + 1]);
    float e2 = expf(ls[i * 3 + 2]);
    const float s0 = 1.0f / (e0 * e0);
    const float s1 = 1.0f / (e1 * e1);
    const float s2 = 1.0f / (e2 * e2);

    const float a0 = 1.0f / (1.0f + expf(-rop[i]));
    const float c0 = 1.0f / (1.0f + expf(-col[i * 3 + 0]));
    const float c1 = 1.0f / (1.0f + expf(-col[i * 3 + 1]));
    const float c2 = 1.0f / (1.0f + expf(-col[i * 3 + 2]));

    const float ms0 = mu0 * s0;
    const float ms1 = mu1 * s1;
    const float ms2 = mu2 * s2;
    const float m2  = mu0 * ms0 + mu1 * ms1 + mu2 * ms2;

    g_sorted[rank * 3 + 0] = make_float4(ms0, ms1, ms2, s0);
    g_sorted[rank * 3 + 1] = make_float4(s1, s2, m2, a0);
    g_sorted[rank * 3 + 2] = make_float4(c0, c1, c2, 0.0f);
}

__device__ __forceinline__ float fast_ex2(float x) {
    float r;
    asm("ex2.approx.ftz.f32 %0, %1;" : "=f"(r) : "f"(x));
    return r;
}

__device__ __forceinline__ float fast_rcp(float x) {
    float r;
    asm("rcp.approx.ftz.f32 %0, %1;" : "=f"(r) : "f"(x));
    return r;
}

__global__ __launch_bounds__(256) void render_kernel(float* __restrict__ out) {
    __shared__ float4 sg[NG * 3];
    const int t = threadIdx.x;
#pragma unroll
    for (int k = t; k < NG * 3; k += 256) sg[k] = g_sorted[k];

    const int pix = blockIdx.x * 256 + t;
    const int y = pix >> 9;      // /512
    const int x = pix & 511;

    float dx = (x + 0.5f - CXc) * (1.0f / FXc);
    float dy = (y + 0.5f - CYc) * (1.0f / FYc);
    const float rn = rsqrtf(fmaf(dx, dx, fmaf(dy, dy, 1.0f)));
    dx *= rn; dy *= rn;
    const float dz = rn;
    const float dxx = dx * dx, dyy = dy * dy, dzz = dz * dz;

    __syncthreads();

    float T = 1.0f, cr = 0.0f, cg = 0.0f, cb = 0.0f;

#pragma unroll 4
    for (int i = 0; i < NG; i++) {
        const float4 p0 = sg[i * 3 + 0];
        const float4 p1 = sg[i * 3 + 1];
        const float4 p2 = sg[i * 3 + 2];

        const float num = fmaf(p0.x, dx, fmaf(p0.y, dy, p0.z * dz));
        const float den = fmaf(p0.w, dxx, fmaf(p1.x, dyy, fmaf(p1.y, dzz, 1e-10f)));
        const float tau = num * fast_rcp(den);

        // mahal = tau^2*den - 2*tau*num + m2  (== sum s_k (d_k*tau - mu_k)^2)
        const float mahal = fmaf(tau, fmaf(tau, den, -(num + num)), p1.z);

        float alpha = p1.w * fast_ex2(mahal * -0.7213475204444817f); // exp(-0.5*mahal)
        if (!(tau > 0.1f)) alpha = 0.0f;

        const float w = T * alpha;
        cr = fmaf(w, p2.x, cr);
        cg = fmaf(w, p2.y, cg);
        cb = fmaf(w, p2.z, cb);
        T  = T - w;
    }

    out[pix * 3 + 0] = cr + T;
    out[pix * 3 + 1] = cg + T;
    out[pix * 3 + 2] = cb + T;
}

extern "C" void kernel_launch(void* const* d_in, const int* in_sizes, int n_in,
                              void* d_out, int out_size) {
    const float* pos = (const float*)d_in[0];
    const float* ls  = (const float*)d_in[1];
    const float* rop = (const float*)d_in[2];
    const float* col = (const float*)d_in[3];
    float* out = (float*)d_out;

    prep_kernel<<<1, NG>>>(pos, ls, rop, col);
    render_kernel<<<(IMG_H * IMG_W) / 256, 256>>>(out);
}

// round 2
// speedup vs baseline: 1.1589x; 1.1589x over previous
#include <cuda_runtime.h>
#include <cuda_bf16.h>

#define IMG_H 512
#define IMG_W 512
#define FXc 500.0f
#define FYc 500.0f
#define CXc 256.0f
#define CYc 256.0f
#define NG  256

// K = 0.5*log2(e); sqrt(K) folded into mu*s params.
#define SQRT_K 0.8493218002880191f
// valid check: num' > 0.1*sqrt(K)*den
#define VALID_C 0.08493218002880191f

typedef unsigned long long u64;

// Packed (duplicated-pair) sorted gaussian params.
// Per gaussian: 5 x ulonglong2 (80B):
//  e0 = { {ms0',ms0'}, {ms1',ms1'} }
//  e1 = { {ms2',ms2'}, {s0,s0} }
//  e2 = { {s1,s1},     {s2,s2} }
//  e3 = { {a0p,a0p},   {c0,c0} }     a0p = sigmoid(op)*exp(-0.5*m2)
//  e4 = { {c1,c1},     {c2,c2} }
__device__ ulonglong2 g_packed[NG * 5];

__global__ void prep_kernel(const float* __restrict__ pos,
                            const float* __restrict__ ls,
                            const float* __restrict__ rop,
                            const float* __restrict__ col) {
    const int i = threadIdx.x;
    __shared__ float zs[NG];
    const float z = pos[i * 3 + 2];
    zs[i] = z;
    __syncthreads();

    // Stable rank = jnp.argsort position (ascending, stable ties).
    int rank = 0;
#pragma unroll 16
    for (int j = 0; j < NG; j++) {
        const float zj = zs[j];
        rank += (zj < z) || (zj == z && j < i);
    }

    const float mu0 = pos[i * 3 + 0];
    const float mu1 = pos[i * 3 + 1];
    const float mu2 = z;

    const float e0 = expf(ls[i * 3 + 0]);
    const float e1 = expf(ls[i * 3 + 1]);
    const float e2 = expf(ls[i * 3 + 2]);
    const float s0 = 1.0f / (e0 * e0);
    const float s1 = 1.0f / (e1 * e1);
    const float s2 = 1.0f / (e2 * e2);

    const float ms0 = mu0 * s0;
    const float ms1 = mu1 * s1;
    const float ms2 = mu2 * s2;
    const float m2  = mu0 * ms0 + mu1 * ms1 + mu2 * ms2;

    const float a0  = 1.0f / (1.0f + expf(-rop[i]));
    const float a0p = a0 * expf(-0.5f * m2);
    const float c0 = 1.0f / (1.0f + expf(-col[i * 3 + 0]));
    const float c1 = 1.0f / (1.0f + expf(-col[i * 3 + 1]));
    const float c2 = 1.0f / (1.0f + expf(-col[i * 3 + 2]));

    float* gp = (float*)&g_packed[rank * 5];
    gp[0]  = ms0 * SQRT_K; gp[1]  = gp[0];
    gp[2]  = ms1 * SQRT_K; gp[3]  = gp[2];
    gp[4]  = ms2 * SQRT_K; gp[5]  = gp[4];
    gp[6]  = s0;           gp[7]  = s0;
    gp[8]  = s1;           gp[9]  = s1;
    gp[10] = s2;           gp[11] = s2;
    gp[12] = a0p;          gp[13] = a0p;
    gp[14] = c0;           gp[15] = c0;
    gp[16] = c1;           gp[17] = c1;
    gp[18] = c2;           gp[19] = c2;
}

__device__ __forceinline__ float fast_ex2(float x) {
    float r;
    asm("ex2.approx.ftz.f32 %0, %1;" : "=f"(r) : "f"(x));
    return r;
}
__device__ __forceinline__ float fast_rcp(float x) {
    float r;
    asm("rcp.approx.ftz.f32 %0, %1;" : "=f"(r) : "f"(x));
    return r;
}
__device__ __forceinline__ u64 fma2(u64 a, u64 b, u64 c) {
    u64 d; asm("fma.rn.f32x2 %0, %1, %2, %3;" : "=l"(d) : "l"(a), "l"(b), "l"(c)); return d;
}
__device__ __forceinline__ u64 mul2(u64 a, u64 b) {
    u64 d; asm("mul.rn.f32x2 %0, %1, %2;" : "=l"(d) : "l"(a), "l"(b)); return d;
}
__device__ __forceinline__ u64 add2(u64 a, u64 b) {
    u64 d; asm("add.rn.f32x2 %0, %1, %2;" : "=l"(d) : "l"(a), "l"(b)); return d;
}
__device__ __forceinline__ u64 pk(float lo, float hi) {
    u64 d; asm("mov.b64 %0, {%1, %2};" : "=l"(d) : "f"(lo), "f"(hi)); return d;
}
__device__ __forceinline__ void upk(float& lo, float& hi, u64 a) {
    asm("mov.b64 {%0, %1}, %2;" : "=f"(lo), "=f"(hi) : "l"(a));
}

__global__ __launch_bounds__(256) void render_kernel(float* __restrict__ out) {
    __shared__ ulonglong2 sg[NG * 5];  // 20 KB
    const int t = threadIdx.x;
#pragma unroll
    for (int k = t; k < NG * 5; k += 256) sg[k] = g_packed[k];

    // One block per image row; each thread renders pixels (2t, 2t+1) of row blockIdx.x.
    const int y  = blockIdx.x;
    const int x0 = 2 * t;
    const int x1 = x0 + 1;

    const float dyr = (y + 0.5f - CYc) * (1.0f / FYc);
    float ax0 = (x0 + 0.5f - CXc) * (1.0f / FXc);
    float ax1 = (x1 + 0.5f - CXc) * (1.0f / FXc);
    const float rn0 = rsqrtf(fmaf(ax0, ax0, fmaf(dyr, dyr, 1.0f)));
    const float rn1 = rsqrtf(fmaf(ax1, ax1, fmaf(dyr, dyr, 1.0f)));
    const float dx0 = ax0 * rn0, dx1 = ax1 * rn1;
    const float dy0 = dyr * rn0, dy1 = dyr * rn1;
    const float dz0 = rn0,       dz1 = rn1;

    const u64 dx2  = pk(dx0, dx1), dy2 = pk(dy0, dy1), dz2 = pk(dz0, dz1);
    const u64 dxx2 = mul2(dx2, dx2), dyy2 = mul2(dy2, dy2), dzz2 = mul2(dz2, dz2);
    const u64 NEG1 = pk(-1.0f, -1.0f);

    __syncthreads();

    u64 T2  = pk(1.0f, 1.0f);
    u64 cr2 = pk(0.0f, 0.0f), cg2 = cr2, cb2 = cr2;

#pragma unroll 4
    for (int i = 0; i < NG; i++) {
        const ulonglong2 e0 = sg[i * 5 + 0];
        const ulonglong2 e1 = sg[i * 5 + 1];
        const ulonglong2 e2 = sg[i * 5 + 2];
        const ulonglong2 e3 = sg[i * 5 + 3];
        const ulonglong2 e4 = sg[i * 5 + 4];

        const u64 num2 = fma2(e0.x, dx2, fma2(e0.y, dy2, mul2(e1.x, dz2)));
        const u64 den2 = fma2(e1.y, dxx2, fma2(e2.x, dyy2, mul2(e2.y, dzz2)));

        float n0, n1, d0, d1, a0p, a0p_;
        upk(n0, n1, num2);
        upk(d0, d1, den2);
        upk(a0p, a0p_, e3.x);

        const float r0 = fast_rcp(d0);
        const float r1 = fast_rcp(d1);

        // alpha = a0p * 2^(num'^2 / den), gated by tau > 0.1  (num' > 0.1*sqrtK*den)
        const float al0 = (n0 > VALID_C * d0) ? a0p * fast_ex2(n0 * n0 * r0) : 0.0f;
        const float al1 = (n1 > VALID_C * d1) ? a0p * fast_ex2(n1 * n1 * r1) : 0.0f;

        const u64 al2 = pk(al0, al1);
        const u64 w2  = mul2(T2, al2);
        cr2 = fma2(w2, e3.y, cr2);
        cg2 = fma2(w2, e4.x, cg2);
        cb2 = fma2(w2, e4.y, cb2);
        T2  = fma2(w2, NEG1, T2);
    }

    // image + T
    const u64 fr2 = add2(cr2, T2);
    const u64 fg2 = add2(cg2, T2);
    const u64 fb2 = add2(cb2, T2);
    float r0, r1, g0, g1, b0, b1;
    upk(r0, r1, fr2);
    upk(g0, g1, fg2);
    upk(b0, b1, fb2);

    // 6 contiguous floats per thread, 8B-aligned -> 3x float2 stores.
    float2* o = (float2*)(out + (size_t)y * (IMG_W * 3) + 6 * t);
    o[0] = make_float2(r0, g0);
    o[1] = make_float2(b0, r1);
    o[2] = make_float2(g1, b1);
}

extern "C" void kernel_launch(void* const* d_in, const int* in_sizes, int n_in,
                              void* d_out, int out_size) {
    const float* pos = (const float*)d_in[0];
    const float* ls  = (const float*)d_in[1];
    const float* rop = (const float*)d_in[2];
    const float* col = (const float*)d_in[3];
    float* out = (float*)d_out;

    prep_kernel<<<1, NG>>>(pos, ls, rop, col);
    render_kernel<<<IMG_H, 256>>>(out);
}

// round 3
// speedup vs baseline: 1.1640x; 1.0044x over previous
#include <cuda_runtime.h>
#include <cuda_bf16.h>

#define IMG_H 512
#define IMG_W 512
#define FXc 500.0f
#define FYc 500.0f
#define CXc 256.0f
#define CYc 256.0f
#define NG  256

// K = 0.5*log2(e) folded as sqrt(K) into mu*s params.
#define SQRT_K 0.8493218002880191f
// valid gate: num' > 0.1*sqrt(K)*den
#define VALID_C 0.08493218002880191f

typedef unsigned long long u64;

// Packed (duplicated-pair) sorted gaussian params, 5 x ulonglong2 each:
//  e0 = { {ms0',ms0'}, {ms1',ms1'} }
//  e1 = { {ms2',ms2'}, {s0,s0} }
//  e2 = { {s1,s1},     {s2,s2} }
//  e3 = { {a0p,a0p},   {c0,c0} }   a0p = sigmoid(op)*exp(-0.5*m2)
//  e4 = { {c1,c1},     {c2,c2} }
__device__ ulonglong2 g_packed[NG * 5];

__global__ void prep_kernel(const float* __restrict__ pos,
                            const float* __restrict__ ls,
                            const float* __restrict__ rop,
                            const float* __restrict__ col) {
    const int i = threadIdx.x;
    __shared__ float zs[NG];
    const float z = pos[i * 3 + 2];
    zs[i] = z;
    __syncthreads();

    int rank = 0;
#pragma unroll 16
    for (int j = 0; j < NG; j++) {
        const float zj = zs[j];
        rank += (zj < z) || (zj == z && j < i);
    }

    const float mu0 = pos[i * 3 + 0];
    const float mu1 = pos[i * 3 + 1];
    const float mu2 = z;

    const float e0 = expf(ls[i * 3 + 0]);
    const float e1 = expf(ls[i * 3 + 1]);
    const float e2 = expf(ls[i * 3 + 2]);
    const float s0 = 1.0f / (e0 * e0);
    const float s1 = 1.0f / (e1 * e1);
    const float s2 = 1.0f / (e2 * e2);

    const float ms0 = mu0 * s0;
    const float ms1 = mu1 * s1;
    const float ms2 = mu2 * s2;
    const float m2  = mu0 * ms0 + mu1 * ms1 + mu2 * ms2;

    const float a0  = 1.0f / (1.0f + expf(-rop[i]));
    const float a0p = a0 * expf(-0.5f * m2);
    const float c0 = 1.0f / (1.0f + expf(-col[i * 3 + 0]));
    const float c1 = 1.0f / (1.0f + expf(-col[i * 3 + 1]));
    const float c2 = 1.0f / (1.0f + expf(-col[i * 3 + 2]));

    float* gp = (float*)&g_packed[rank * 5];
    gp[0]  = ms0 * SQRT_K; gp[1]  = gp[0];
    gp[2]  = ms1 * SQRT_K; gp[3]  = gp[2];
    gp[4]  = ms2 * SQRT_K; gp[5]  = gp[4];
    gp[6]  = s0;           gp[7]  = s0;
    gp[8]  = s1;           gp[9]  = s1;
    gp[10] = s2;           gp[11] = s2;
    gp[12] = a0p;          gp[13] = a0p;
    gp[14] = c0;           gp[15] = c0;
    gp[16] = c1;           gp[17] = c1;
    gp[18] = c2;           gp[19] = c2;
}

__device__ __forceinline__ float fast_ex2(float x) {
    float r;
    asm("ex2.approx.ftz.f32 %0, %1;" : "=f"(r) : "f"(x));
    return r;
}
__device__ __forceinline__ float fast_rcp(float x) {
    float r;
    asm("rcp.approx.ftz.f32 %0, %1;" : "=f"(r) : "f"(x));
    return r;
}
__device__ __forceinline__ u64 fma2(u64 a, u64 b, u64 c) {
    u64 d; asm("fma.rn.f32x2 %0, %1, %2, %3;" : "=l"(d) : "l"(a), "l"(b), "l"(c)); return d;
}
__device__ __forceinline__ u64 mul2(u64 a, u64 b) {
    u64 d; asm("mul.rn.f32x2 %0, %1, %2;" : "=l"(d) : "l"(a), "l"(b)); return d;
}
__device__ __forceinline__ u64 add2(u64 a, u64 b) {
    u64 d; asm("add.rn.f32x2 %0, %1, %2;" : "=l"(d) : "l"(a), "l"(b)); return d;
}
__device__ __forceinline__ u64 pk(float lo, float hi) {
    u64 d; asm("mov.b64 %0, {%1, %2};" : "=l"(d) : "f"(lo), "f"(hi)); return d;
}
__device__ __forceinline__ void upk(float& lo, float& hi, u64 a) {
    asm("mov.b64 {%0, %1}, %2;" : "=f"(lo), "=f"(hi) : "l"(a));
}

// One block = one image row (128 threads, 4 px/thread, two packed chains).
__global__ __launch_bounds__(128) void render_kernel(float* __restrict__ out) {
    __shared__ ulonglong2 sg[NG * 5];  // 20 KB
    const int t = threadIdx.x;
#pragma unroll
    for (int k = t; k < NG * 5; k += 128) sg[k] = g_packed[k];

    const int y  = blockIdx.x;
    const int xb = 4 * t;

    const float dyr = (y + 0.5f - CYc) * (1.0f / FYc);
    float dxs[4], dys[4], dzs[4];
#pragma unroll
    for (int p = 0; p < 4; p++) {
        const float ax = (xb + p + 0.5f - CXc) * (1.0f / FXc);
        const float rn = rsqrtf(fmaf(ax, ax, fmaf(dyr, dyr, 1.0f)));
        dxs[p] = ax * rn; dys[p] = dyr * rn; dzs[p] = rn;
    }

    const u64 dxA = pk(dxs[0], dxs[1]), dxB = pk(dxs[2], dxs[3]);
    const u64 dyA = pk(dys[0], dys[1]), dyB = pk(dys[2], dys[3]);
    const u64 dzA = pk(dzs[0], dzs[1]), dzB = pk(dzs[2], dzs[3]);
    const u64 dxxA = mul2(dxA, dxA), dxxB = mul2(dxB, dxB);
    const u64 dyyA = mul2(dyA, dyA), dyyB = mul2(dyB, dyB);
    const u64 dzzA = mul2(dzA, dzA), dzzB = mul2(dzB, dzB);
    const u64 NEG1 = pk(-1.0f, -1.0f);

    __syncthreads();

    u64 TA = pk(1.0f, 1.0f), TB = TA;
    u64 crA = pk(0.0f, 0.0f), cgA = crA, cbA = crA;
    u64 crB = crA, cgB = crA, cbB = crA;

#pragma unroll 4
    for (int i = 0; i < NG; i++) {
        const ulonglong2 e0 = sg[i * 5 + 0];
        const ulonglong2 e1 = sg[i * 5 + 1];
        const ulonglong2 e2 = sg[i * 5 + 2];
        const ulonglong2 e3 = sg[i * 5 + 3];
        const ulonglong2 e4 = sg[i * 5 + 4];

        const u64 numA = fma2(e0.x, dxA, fma2(e0.y, dyA, mul2(e1.x, dzA)));
        const u64 numB = fma2(e0.x, dxB, fma2(e0.y, dyB, mul2(e1.x, dzB)));
        const u64 denA = fma2(e1.y, dxxA, fma2(e2.x, dyyA, mul2(e2.y, dzzA)));
        const u64 denB = fma2(e1.y, dxxB, fma2(e2.x, dyyB, mul2(e2.y, dzzB)));
        const u64 nnA = mul2(numA, numA);
        const u64 nnB = mul2(numB, numB);

        float nA0, nA1, nB0, nB1, dA0, dA1, dB0, dB1;
        float qA0, qA1, qB0, qB1, a0p, a0p_;
        upk(nA0, nA1, numA); upk(nB0, nB1, numB);
        upk(dA0, dA1, denA); upk(dB0, dB1, denB);
        upk(qA0, qA1, nnA);  upk(qB0, qB1, nnB);
        upk(a0p, a0p_, e3.x);

        const float rA0 = fast_rcp(dA0), rA1 = fast_rcp(dA1);
        const float rB0 = fast_rcp(dB0), rB1 = fast_rcp(dB1);

        const float xA0 = fast_ex2(qA0 * rA0), xA1 = fast_ex2(qA1 * rA1);
        const float xB0 = fast_ex2(qB0 * rB0), xB1 = fast_ex2(qB1 * rB1);

        const float alA0 = (nA0 > VALID_C * dA0) ? a0p * xA0 : 0.0f;
        const float alA1 = (nA1 > VALID_C * dA1) ? a0p * xA1 : 0.0f;
        const float alB0 = (nB0 > VALID_C * dB0) ? a0p * xB0 : 0.0f;
        const float alB1 = (nB1 > VALID_C * dB1) ? a0p * xB1 : 0.0f;

        const u64 wA = mul2(TA, pk(alA0, alA1));
        const u64 wB = mul2(TB, pk(alB0, alB1));
        crA = fma2(wA, e3.y, crA);  crB = fma2(wB, e3.y, crB);
        cgA = fma2(wA, e4.x, cgA);  cgB = fma2(wB, e4.x, cgB);
        cbA = fma2(wA, e4.y, cbA);  cbB = fma2(wB, e4.y, cbB);
        TA  = fma2(wA, NEG1, TA);   TB  = fma2(wB, NEG1, TB);
    }

    const u64 frA = add2(crA, TA), fgA = add2(cgA, TA), fbA = add2(cbA, TA);
    const u64 frB = add2(crB, TB), fgB = add2(cgB, TB), fbB = add2(cbB, TB);
    float rA0, rA1, gA0, gA1, bA0, bA1;
    float rB0, rB1, gB0, gB1, bB0, bB1;
    upk(rA0, rA1, frA); upk(gA0, gA1, fgA); upk(bA0, bA1, fbA);
    upk(rB0, rB1, frB); upk(gB0, gB1, fgB); upk(bB0, bB1, fbB);

    // 12 contiguous floats per thread (16B aligned) -> 3x float4 stores.
    float4* o = (float4*)(out + (size_t)y * (IMG_W * 3) + 12 * t);
    o[0] = make_float4(rA0, gA0, bA0, rA1);
    o[1] = make_float4(gA1, bA1, rB0, gB0);
    o[2] = make_float4(bB0, rB1, gB1, bB1);
}

extern "C" void kernel_launch(void* const* d_in, const int* in_sizes, int n_in,
                              void* d_out, int out_size) {
    const float* pos = (const float*)d_in[0];
    const float* ls  = (const float*)d_in[1];
    const float* rop = (const float*)d_in[2];
    const float* col = (const float*)d_in[3];
    float* out = (float*)d_out;

    prep_kernel<<<1, NG>>>(pos, ls, rop, col);
    render_kernel<<<IMG_H, 128>>>(out);
}

// round 4
// speedup vs baseline: 1.3204x; 1.1344x over previous
#include <cuda_runtime.h>
#include <cuda_bf16.h>

#define IMG_H 512
#define IMG_W 512
#define FXc 500.0f
#define FYc 500.0f
#define CXc 256.0f
#define CYc 256.0f
#define NG  256

// K = 0.5*log2(e) folded as sqrt(K) into mu*s params.
#define SQRT_K 0.8493218002880191f
// valid gate: num' > 0.1*sqrt(K)*den
#define VALID_C 0.08493218002880191f

typedef unsigned long long u64;

// Packed (duplicated-pair) sorted gaussian params, 5 x ulonglong2 each:
//  e0 = { {ms0',ms0'}, {ms1',ms1'} }
//  e1 = { {ms2',ms2'}, {s0,s0} }
//  e2 = { {s1,s1},     {s2,s2} }
//  e3 = { {la,la},     {c0,c0} }   la = log2( sigmoid(op)*exp(-0.5*m2) )
//  e4 = { {c1,c1},     {c2,c2} }
__device__ ulonglong2 g_packed[NG * 5];

__global__ void prep_kernel(const float* __restrict__ pos,
                            const float* __restrict__ ls,
                            const float* __restrict__ rop,
                            const float* __restrict__ col) {
    const int i = threadIdx.x;
    __shared__ float zs[NG];
    const float z = pos[i * 3 + 2];
    zs[i] = z;
    __syncthreads();

    int rank = 0;
#pragma unroll 16
    for (int j = 0; j < NG; j++) {
        const float zj = zs[j];
        rank += (zj < z) || (zj == z && j < i);
    }

    const float mu0 = pos[i * 3 + 0];
    const float mu1 = pos[i * 3 + 1];
    const float mu2 = z;

    const float e0 = expf(ls[i * 3 + 0]);
    const float e1 = expf(ls[i * 3 + 1]);
    const float e2 = expf(ls[i * 3 + 2]);
    const float s0 = 1.0f / (e0 * e0);
    const float s1 = 1.0f / (e1 * e1);
    const float s2 = 1.0f / (e2 * e2);

    const float ms0 = mu0 * s0;
    const float ms1 = mu1 * s1;
    const float ms2 = mu2 * s2;
    const float m2  = mu0 * ms0 + mu1 * ms1 + mu2 * ms2;

    const float a0  = 1.0f / (1.0f + expf(-rop[i]));
    // la = log2(a0 * exp(-0.5*m2)) = log2(a0) - 0.5*m2*log2(e)
    const float la  = log2f(a0) - 0.72134752044448170367f * m2;
    const float c0 = 1.0f / (1.0f + expf(-col[i * 3 + 0]));
    const float c1 = 1.0f / (1.0f + expf(-col[i * 3 + 1]));
    const float c2 = 1.0f / (1.0f + expf(-col[i * 3 + 2]));

    float* gp = (float*)&g_packed[rank * 5];
    gp[0]  = ms0 * SQRT_K; gp[1]  = gp[0];
    gp[2]  = ms1 * SQRT_K; gp[3]  = gp[2];
    gp[4]  = ms2 * SQRT_K; gp[5]  = gp[4];
    gp[6]  = s0;           gp[7]  = s0;
    gp[8]  = s1;           gp[9]  = s1;
    gp[10] = s2;           gp[11] = s2;
    gp[12] = la;           gp[13] = la;
    gp[14] = c0;           gp[15] = c0;
    gp[16] = c1;           gp[17] = c1;
    gp[18] = c2;           gp[19] = c2;
}

__device__ __forceinline__ float fast_ex2(float x) {
    float r;
    asm("ex2.approx.ftz.f32 %0, %1;" : "=f"(r) : "f"(x));
    return r;
}
__device__ __forceinline__ float fast_rcp(float x) {
    float r;
    asm("rcp.approx.ftz.f32 %0, %1;" : "=f"(r) : "f"(x));
    return r;
}
__device__ __forceinline__ u64 fma2(u64 a, u64 b, u64 c) {
    u64 d; asm("fma.rn.f32x2 %0, %1, %2, %3;" : "=l"(d) : "l"(a), "l"(b), "l"(c)); return d;
}
__device__ __forceinline__ u64 mul2(u64 a, u64 b) {
    u64 d; asm("mul.rn.f32x2 %0, %1, %2;" : "=l"(d) : "l"(a), "l"(b)); return d;
}
__device__ __forceinline__ u64 add2(u64 a, u64 b) {
    u64 d; asm("add.rn.f32x2 %0, %1, %2;" : "=l"(d) : "l"(a), "l"(b)); return d;
}
__device__ __forceinline__ u64 pk(float lo, float hi) {
    u64 d; asm("mov.b64 %0, {%1, %2};" : "=l"(d) : "f"(lo), "f"(hi)); return d;
}
__device__ __forceinline__ void upk(float& lo, float& hi, u64 a) {
    asm("mov.b64 {%0, %1}, %2;" : "=f"(lo), "=f"(hi) : "l"(a));
}

// One block = half an image row. 128 threads, 2 px/thread (one packed chain).
__global__ __launch_bounds__(128) void render_kernel(float* __restrict__ out) {
    __shared__ ulonglong2 sg[NG * 5];  // 20 KB
    const int t = threadIdx.x;
#pragma unroll
    for (int k = t; k < NG * 5; k += 128) sg[k] = g_packed[k];

    const int y  = blockIdx.x >> 1;
    const int x0 = ((blockIdx.x & 1) << 8) + 2 * t;   // 2t or 256+2t
    const int x1 = x0 + 1;

    const float dyr = (y + 0.5f - CYc) * (1.0f / FYc);
    float ax0 = (x0 + 0.5f - CXc) * (1.0f / FXc);
    float ax1 = (x1 + 0.5f - CXc) * (1.0f / FXc);
    const float rn0 = rsqrtf(fmaf(ax0, ax0, fmaf(dyr, dyr, 1.0f)));
    const float rn1 = rsqrtf(fmaf(ax1, ax1, fmaf(dyr, dyr, 1.0f)));

    const u64 dx2  = pk(ax0 * rn0, ax1 * rn1);
    const u64 dy2  = pk(dyr * rn0, dyr * rn1);
    const u64 dz2  = pk(rn0, rn1);
    const u64 dxx2 = mul2(dx2, dx2), dyy2 = mul2(dy2, dy2), dzz2 = mul2(dz2, dz2);
    const u64 NEG1 = pk(-1.0f, -1.0f);

    __syncthreads();

    u64 T2  = pk(1.0f, 1.0f);
    u64 cr2 = pk(0.0f, 0.0f), cg2 = cr2, cb2 = cr2;

    for (int ib = 0; ib < NG; ib += 16) {
        // Warp-level early termination: remaining contribution bounded by T < 1e-7.
        float t0, t1;
        upk(t0, t1, T2);
        if (__all_sync(0xffffffffu, fmaxf(t0, t1) < 1e-7f)) break;

#pragma unroll
        for (int j = 0; j < 16; j++) {
            const int i = ib + j;
            const ulonglong2 e0 = sg[i * 5 + 0];
            const ulonglong2 e1 = sg[i * 5 + 1];
            const ulonglong2 e2 = sg[i * 5 + 2];
            const ulonglong2 e3 = sg[i * 5 + 3];
            const ulonglong2 e4 = sg[i * 5 + 4];

            const u64 num2 = fma2(e0.x, dx2, fma2(e0.y, dy2, mul2(e1.x, dz2)));
            const u64 den2 = fma2(e1.y, dxx2, fma2(e2.x, dyy2, mul2(e2.y, dzz2)));
            const u64 nn2  = mul2(num2, num2);

            float n0, n1, d0, d1, q0, q1, la, la_;
            upk(n0, n1, num2);
            upk(d0, d1, den2);
            upk(q0, q1, nn2);
            upk(la, la_, e3.x);

            // Batched reciprocal: one MUFU rcp serves both pixels.
            const float r  = fast_rcp(d0 * d1);
            const float i0 = r * d1;
            const float i1 = r * d0;

            // alpha = 2^(q/d + la), gated: invalid -> arg=-1e30 -> ex2 -> 0
            const float arg0 = (n0 > VALID_C * d0) ? fmaf(q0, i0, la) : -1e30f;
            const float arg1 = (n1 > VALID_C * d1) ? fmaf(q1, i1, la) : -1e30f;
            const float al0 = fast_ex2(arg0);
            const float al1 = fast_ex2(arg1);

            const u64 w2 = mul2(T2, pk(al0, al1));
            cr2 = fma2(w2, e3.y, cr2);
            cg2 = fma2(w2, e4.x, cg2);
            cb2 = fma2(w2, e4.y, cb2);
            T2  = fma2(w2, NEG1, T2);
        }
    }

    const u64 fr2 = add2(cr2, T2);
    const u64 fg2 = add2(cg2, T2);
    const u64 fb2 = add2(cb2, T2);
    float r0, r1, g0, g1, b0, b1;
    upk(r0, r1, fr2);
    upk(g0, g1, fg2);
    upk(b0, b1, fb2);

    float2* o = (float2*)(out + (size_t)y * (IMG_W * 3) + 3 * x0);
    o[0] = make_float2(r0, g0);
    o[1] = make_float2(b0, r1);
    o[2] = make_float2(g1, b1);
}

extern "C" void kernel_launch(void* const* d_in, const int* in_sizes, int n_in,
                              void* d_out, int out_size) {
    const float* pos = (const float*)d_in[0];
    const float* ls  = (const float*)d_in[1];
    const float* rop = (const float*)d_in[2];
    const float* col = (const float*)d_in[3];
    float* out = (float*)d_out;

    prep_kernel<<<1, NG>>>(pos, ls, rop, col);
    render_kernel<<<IMG_H * 2, 128>>>(out);
}

// round 5
// speedup vs baseline: 1.6583x; 1.2559x over previous
#include <cuda_runtime.h>
#include <cuda_bf16.h>

#define IMG_H 512
#define IMG_W 512
#define FXc 500.0f
#define FYc 500.0f
#define CXc 256.0f
#define CYc 256.0f
#define NG  256

// K = 0.5*log2(e) folded as sqrt(K) into mu*s params.
#define SQRT_K 0.8493218002880191f
// valid gate: num' > 0.1*sqrt(K)*den
#define VALID_C 0.08493218002880191f

typedef unsigned long long u64;

// Compacted, padded, packed (duplicated-pair) sorted gaussian params.
// Per gaussian: 5 x ulonglong2:
//  e0 = { {ms0',ms0'}, {ms1',ms1'} }
//  e1 = { {ms2',ms2'}, {s0,s0} }
//  e2 = { {s1,s1},     {s2,s2} }
//  e3 = { {la,la},     {c0,c0} }   la = log2( sigmoid(op)*exp(-0.5*m2) )
//  e4 = { {c1,c1},     {c2,c2} }
__device__ ulonglong2 g_packed[(NG + 8) * 5];
__device__ int d_npad;

__global__ void prep_kernel(const float* __restrict__ pos,
                            const float* __restrict__ ls,
                            const float* __restrict__ rop,
                            const float* __restrict__ col) {
    const int i = threadIdx.x;
    __shared__ float zs[NG];
    __shared__ int visr[NG];
    const float z = pos[i * 3 + 2];
    zs[i] = z;
    __syncthreads();

    // Stable rank = jnp.argsort position (ascending, stable ties).
    int rank = 0;
#pragma unroll 16
    for (int j = 0; j < NG; j++) {
        const float zj = zs[j];
        rank += (zj < z) || (zj == z && j < i);
    }

    const float mu0 = pos[i * 3 + 0];
    const float mu1 = pos[i * 3 + 1];
    const float mu2 = z;

    const float e0 = expf(ls[i * 3 + 0]);
    const float e1 = expf(ls[i * 3 + 1]);
    const float e2 = expf(ls[i * 3 + 2]);
    const float s0 = 1.0f / (e0 * e0);
    const float s1 = 1.0f / (e1 * e1);
    const float s2 = 1.0f / (e2 * e2);

    const float ms0 = mu0 * s0;
    const float ms1 = mu1 * s1;
    const float ms2 = mu2 * s2;
    const float m2  = mu0 * ms0 + mu1 * ms1 + mu2 * ms2;

    const float a0  = 1.0f / (1.0f + expf(-rop[i]));
    const float la  = log2f(a0) - 0.72134752044448170367f * m2;
    const float c0 = 1.0f / (1.0f + expf(-col[i * 3 + 0]));
    const float c1 = 1.0f / (1.0f + expf(-col[i * 3 + 1]));
    const float c2 = 1.0f / (1.0f + expf(-col[i * 3 + 2]));

    // EXACT frustum cull. Unnormalized dirs d=(dx,dy,1), dx,dy in [-R,R].
    // num_u = ms·d is linear -> max at corner: num_max = ms2 + R(|ms0|+|ms1|).
    // Render gate: num_u > VALID_C * den_u * rn, with den_u >= s2, rn >= 0.81.
    // If num_max <= VALID_C * s2 * 0.81, alpha == 0 at every pixel.
    const float R = 0.511f;
    const float num_max = ms2 + R * (fabsf(ms0) + fabsf(ms1));
    const int vis = (num_max > VALID_C * s2 * 0.81f) ? 1 : 0;

    visr[rank] = vis;
    __syncthreads();

    int cidx = 0, total = 0;
#pragma unroll 16
    for (int j = 0; j < NG; j++) {
        const int v = visr[j];
        cidx  += (j < rank) ? v : 0;
        total += v;
    }

    if (vis) {
        float* gp = (float*)&g_packed[cidx * 5];
        gp[0]  = ms0 * SQRT_K; gp[1]  = gp[0];
        gp[2]  = ms1 * SQRT_K; gp[3]  = gp[2];
        gp[4]  = ms2 * SQRT_K; gp[5]  = gp[4];
        gp[6]  = s0;           gp[7]  = s0;
        gp[8]  = s1;           gp[9]  = s1;
        gp[10] = s2;           gp[11] = s2;
        gp[12] = la;           gp[13] = la;
        gp[14] = c0;           gp[15] = c0;
        gp[16] = c1;           gp[17] = c1;
        gp[18] = c2;           gp[19] = c2;
    }

    const int npad = (total + 7) & ~7;
    // Exact no-op pad entries: num=0 fails gate, alpha=0.
    if (i < npad - total) {
        float* gp = (float*)&g_packed[(total + i) * 5];
#pragma unroll
        for (int k = 0; k < 20; k++) gp[k] = 0.0f;
        gp[6] = gp[7] = gp[8] = gp[9] = gp[10] = gp[11] = 1.0f;  // s=1 -> den>0
        gp[12] = gp[13] = -100.0f;                                // la (unused)
    }
    if (i == 0) d_npad = npad;
}

__device__ __forceinline__ float fast_ex2(float x) {
    float r;
    asm("ex2.approx.ftz.f32 %0, %1;" : "=f"(r) : "f"(x));
    return r;
}
__device__ __forceinline__ float fast_rcp(float x) {
    float r;
    asm("rcp.approx.ftz.f32 %0, %1;" : "=f"(r) : "f"(x));
    return r;
}
__device__ __forceinline__ u64 fma2(u64 a, u64 b, u64 c) {
    u64 d; asm("fma.rn.f32x2 %0, %1, %2, %3;" : "=l"(d) : "l"(a), "l"(b), "l"(c)); return d;
}
__device__ __forceinline__ u64 mul2(u64 a, u64 b) {
    u64 d; asm("mul.rn.f32x2 %0, %1, %2;" : "=l"(d) : "l"(a), "l"(b)); return d;
}
__device__ __forceinline__ u64 add2(u64 a, u64 b) {
    u64 d; asm("add.rn.f32x2 %0, %1, %2;" : "=l"(d) : "l"(a), "l"(b)); return d;
}
__device__ __forceinline__ u64 pk(float lo, float hi) {
    u64 d; asm("mov.b64 %0, {%1, %2};" : "=l"(d) : "f"(lo), "f"(hi)); return d;
}
__device__ __forceinline__ void upk(float& lo, float& hi, u64 a) {
    asm("mov.b64 {%0, %1}, %2;" : "=f"(lo), "=f"(hi) : "l"(a));
}

// One block = half an image row. 128 threads, 2 px/thread (one packed chain).
__global__ __launch_bounds__(128) void render_kernel(float* __restrict__ out) {
    __shared__ ulonglong2 sg[(NG + 8) * 5];
    const int t = threadIdx.x;
    const int npad = d_npad;
#pragma unroll
    for (int k = t; k < (NG + 8) * 5; k += 128) {
        if (k < npad * 5) sg[k] = g_packed[k];
    }

    const int y  = blockIdx.x >> 1;
    const int x0 = ((blockIdx.x & 1) << 8) + 2 * t;
    const int x1 = x0 + 1;

    const float dyr = (y + 0.5f - CYc) * (1.0f / FYc);
    float ax0 = (x0 + 0.5f - CXc) * (1.0f / FXc);
    float ax1 = (x1 + 0.5f - CXc) * (1.0f / FXc);
    const float rn0 = rsqrtf(fmaf(ax0, ax0, fmaf(dyr, dyr, 1.0f)));
    const float rn1 = rsqrtf(fmaf(ax1, ax1, fmaf(dyr, dyr, 1.0f)));

    const u64 dx2  = pk(ax0 * rn0, ax1 * rn1);
    const u64 dy2  = pk(dyr * rn0, dyr * rn1);
    const u64 dz2  = pk(rn0, rn1);
    const u64 dxx2 = mul2(dx2, dx2), dyy2 = mul2(dy2, dy2), dzz2 = mul2(dz2, dz2);
    const u64 NEG1 = pk(-1.0f, -1.0f);
    const u64 NVC2 = pk(-VALID_C, -VALID_C);

    __syncthreads();

    u64 T2  = pk(1.0f, 1.0f);
    u64 cr2 = pk(0.0f, 0.0f), cg2 = cr2, cb2 = cr2;

    for (int ib = 0; ib < npad; ib += 8) {
        // Warp-level early termination (remaining contribution < 1e-7 abs).
        float t0, t1;
        upk(t0, t1, T2);
        if (__all_sync(0xffffffffu, fmaxf(t0, t1) < 1e-7f)) break;

#pragma unroll
        for (int j = 0; j < 8; j++) {
            const int i = ib + j;
            const ulonglong2 e0 = sg[i * 5 + 0];
            const ulonglong2 e1 = sg[i * 5 + 1];
            const ulonglong2 e2 = sg[i * 5 + 2];
            const ulonglong2 e3 = sg[i * 5 + 3];
            const ulonglong2 e4 = sg[i * 5 + 4];

            const u64 num2 = fma2(e0.x, dx2, fma2(e0.y, dy2, mul2(e1.x, dz2)));
            const u64 den2 = fma2(e1.y, dxx2, fma2(e2.x, dyy2, mul2(e2.y, dzz2)));
            const u64 nn2  = mul2(num2, num2);
            const u64 gg2  = fma2(den2, NVC2, num2);   // >0 <=> tau gate passes

            float g0, g1, d0, d1, q0, q1, la, la_;
            upk(g0, g1, gg2);
            upk(d0, d1, den2);
            upk(q0, q1, nn2);
            upk(la, la_, e3.x);

            // Batched reciprocal: one MUFU rcp serves both pixels.
            const float r  = fast_rcp(d0 * d1);
            const float i0 = r * d1;
            const float i1 = r * d0;

            const float arg0 = (g0 > 0.0f) ? fmaf(q0, i0, la) : -1e30f;
            const float arg1 = (g1 > 0.0f) ? fmaf(q1, i1, la) : -1e30f;
            const float al0 = fast_ex2(arg0);
            const float al1 = fast_ex2(arg1);

            const u64 w2 = mul2(T2, pk(al0, al1));
            cr2 = fma2(w2, e3.y, cr2);
            cg2 = fma2(w2, e4.x, cg2);
            cb2 = fma2(w2, e4.y, cb2);
            T2  = fma2(w2, NEG1, T2);
        }
    }

    const u64 fr2 = add2(cr2, T2);
    const u64 fg2 = add2(cg2, T2);
    const u64 fb2 = add2(cb2, T2);
    float r0, r1, g0, g1, b0, b1;
    upk(r0, r1, fr2);
    upk(g0, g1, fg2);
    upk(b0, b1, fb2);

    float2* o = (float2*)(out + (size_t)y * (IMG_W * 3) + 3 * x0);
    o[0] = make_float2(r0, g0);
    o[1] = make_float2(b0, r1);
    o[2] = make_float2(g1, b1);
}

extern "C" void kernel_launch(void* const* d_in, const int* in_sizes, int n_in,
                              void* d_out, int out_size) {
    const float* pos = (const float*)d_in[0];
    const float* ls  = (const float*)d_in[1];
    const float* rop = (const float*)d_in[2];
    const float* col = (const float*)d_in[3];
    float* out = (float*)d_out;

    prep_kernel<<<1, NG>>>(pos, ls, rop, col);
    render_kernel<<<IMG_H * 2, 128>>>(out);
}